// round 9
// baseline (speedup 1.0000x reference)
#include <cuda_runtime.h>
#include <cuda_fp16.h>
#include <math.h>

#define IMG_H 2048
#define IMG_W 2048
#define NIMG  4
#define NPIX  (IMG_H * IMG_W)
#define OUTHW 2038                 /* 2048 - 11 + 1 */

#define C1V 6.5025f
#define C2V 58.5225f

#define TILE_W 32
#define TILE_H 64
#define HALO_H (TILE_H + 10)       /* 74 */
#define SP_STRIDE 49               /* half2 units; bank step 17 (odd) -> conflict-free */
#define H_STRIDE  33               /* ull units */
#define TOTAL_BLOCKS (64 * 32 * 4) /* 8192 */

typedef unsigned long long ull;

/* dynamic smem layout (bytes) */
#define OFF_SPT 0                                  /* half2[74*49] = 14504 B */
#define OFF_HPT 14504                              /* ull  [74*33] = 19536 B */
#define OFF_HSQ (14504 + 19536)                    /* ull  [74*33] = 19536 B */
#define SMEM_BYTES (OFF_HSQ + 19536)               /* 53576 -> 4 blocks/SM   */

#define PACKF2(out, lo, hi) \
    asm("mov.b64 %0, {%1, %2};" : "=l"(out) : "f"(lo), "f"(hi))
#define UNPACKF2(lo, hi, in) \
    asm("mov.b64 {%0, %1}, %2;" : "=f"(lo), "=f"(hi) : "l"(in))
#define FMA2(d, a, b, c) \
    asm("fma.rn.f32x2 %0, %1, %2, %3;" : "=l"(d) : "l"(a), "l"(b), "l"(c))
#define ADD2(d, a, b) \
    asm("add.rn.f32x2 %0, %1, %2;" : "=l"(d) : "l"(a), "l"(b))

// accumulator slots (doubles), hashed:
//   [0..15] l1  [16..31] gx  [32..47] gy  [48..63] range
//   [64..95] sum_p[b][h8]  [96..127] sum_t  [128..159] sumsq_p
//   [160..191] sumsq_t  [192..223] mse8  [224..255] ssim
__device__ double g_acc[256];
__device__ unsigned g_ticket;

__device__ __forceinline__ float quant_u8(float x) {
    return floorf(__saturatef((x + 1.0f) * 0.5f) * 255.0f);
}

// ---------------------------------------------------------------------------
__global__ __launch_bounds__(256, 4) void main_kernel(
    const float* __restrict__ pred, const float* __restrict__ tgt,
    float* __restrict__ out)
{
    extern __shared__ unsigned char smraw[];
    __half2* sPT = (__half2*)(smraw + OFF_SPT);
    ull*     hPT = (ull*)(smraw + OFF_HPT);
    ull*     hSQ = (ull*)(smraw + OFF_HSQ);
    float*   sD  = (float*)(smraw + OFF_HPT);  // alias: 65x34 d-values, dead before hPT written
    __shared__ ull  redu[8][5];
    __shared__ float redf[8];
    __shared__ unsigned s_ticket;

    const int tid = threadIdx.x;
    const int lane = tid & 31, warp = tid >> 5;
    const int x0 = blockIdx.x * TILE_W;
    const int y0 = blockIdx.y * TILE_H;
    const int b  = blockIdx.z;
    const size_t base = (size_t)b * NPIX;
    const int h16 = (blockIdx.x + blockIdx.y) & 15;
    const int h8  = (blockIdx.x + blockIdx.y) & 7;

    float a_l1 = 0.f, a_gx = 0.f, a_gy = 0.f, a_rng = 0.f;
    float a_sp = 0.f, a_st = 0.f, a_spp = 0.f, a_stt = 0.f, a_mse = 0.f;

    // ---- phase 0a: interior (64 rows x 8 quads = 512 float4 items, 2/thread):
    //      unconditional stats + stores
    #pragma unroll
    for (int k = 0; k < 2; ++k) {
        const int i = tid + k * 256;            // 0..511
        const int r = i >> 3, q = i & 7;        // r 0..63, q 0..7
        const size_t off = base + (size_t)(y0 + r) * IMG_W + (x0 + 4 * q);
        const float4 p4 = *(const float4*)(pred + off);
        const float4 t4 = *(const float4*)(tgt  + off);
        const float pe[4] = { p4.x, p4.y, p4.z, p4.w };
        const float te[4] = { t4.x, t4.y, t4.z, t4.w };
        #pragma unroll
        for (int e = 0; e < 4; ++e) {
            const float p = pe[e], t = te[e];
            const float qp = quant_u8(p), qt = quant_u8(t);
            const int c = 4 * q + e;
            sPT[r * SP_STRIDE + c] = __floats2half2_rn(qp, qt);
            const float d = p - t;
            sD[r * 34 + c] = d;                 // r<64, c<32 always in range
            a_l1  += fabsf(d);
            a_rng += fmaxf(fabsf(p) - 1.f, 0.f);
            a_sp  += p;  a_st += t;
            a_spp = fmaf(p, p, a_spp);
            a_stt = fmaf(t, t, a_stt);
            const float qd = qp - qt;
            a_mse = fmaf(qd, qd, a_mse);
        }
    }

    // ---- phase 0b: halo only (rows 64..73 full width; cols 32..43 of rows 0..63)
    for (int i2 = tid; i2 < 302; i2 += 256) {
        int r, q;
        if (i2 < 110) { const int rr = i2 / 11; r = 64 + rr; q = i2 - rr * 11; }
        else          { const int j = i2 - 110; const int jr = j / 3; r = jr; q = 8 + (j - 3 * jr); }
        const int gy_ = y0 + r, cb = x0 + 4 * q;
        float4 p4 = make_float4(0.f, 0.f, 0.f, 0.f);
        float4 t4 = make_float4(0.f, 0.f, 0.f, 0.f);
        if (gy_ < IMG_H && cb < IMG_W) {
            const size_t off = base + (size_t)gy_ * IMG_W + cb;
            p4 = *(const float4*)(pred + off);
            t4 = *(const float4*)(tgt  + off);
        }
        const float pe[4] = { p4.x, p4.y, p4.z, p4.w };
        const float te[4] = { t4.x, t4.y, t4.z, t4.w };
        #pragma unroll
        for (int e = 0; e < 4; ++e) {
            const float p = pe[e], t = te[e];
            const int c = 4 * q + e;
            sPT[r * SP_STRIDE + c] = __floats2half2_rn(quant_u8(p), quant_u8(t));
            if (r < 65 && c < 34) sD[r * 34 + c] = p - t;   // bottom row 64 / cols 32,33
        }
    }
    __syncthreads();

    // ---- phase 1: gradient stats on the owned interior (64x32)
    for (int i = tid; i < TILE_H * TILE_W; i += 256) {
        const int r = i >> 5, c = i & 31;
        const float d = sD[r * 34 + c];
        if (y0 + r < IMG_H - 1) a_gx += fabsf(d - sD[(r + 1) * 34 + c]);
        if (x0 + c < IMG_W - 1) a_gy += fabsf(d - sD[r * 34 + c + 1]);
    }

    // ---- flush the 9 pointwise stats (frees registers for conv phases)
    {
        ull v[5];
        PACKF2(v[0], a_l1, a_gx);
        PACKF2(v[1], a_gy, a_rng);
        PACKF2(v[2], a_sp, a_st);
        PACKF2(v[3], a_spp, a_stt);
        PACKF2(v[4], a_mse, 0.f);
        #pragma unroll
        for (int i = 0; i < 5; ++i) {
            #pragma unroll
            for (int o = 16; o; o >>= 1) {
                ull t2 = __shfl_down_sync(0xffffffffu, v[i], o);
                ADD2(v[i], v[i], t2);
            }
            if (lane == 0) redu[warp][i] = v[i];
        }
    }
    __syncthreads();     // sD reads done -> hPT/hSQ writable; redu published
    if (warp == 0 && lane < 5) {
        ull s2 = redu[0][lane];
        #pragma unroll
        for (int w2 = 1; w2 < 8; ++w2) ADD2(s2, s2, redu[w2][lane]);
        float va, vb; UNPACKF2(va, vb, s2);
        int sa, sb;
        switch (lane) {
            case 0: sa = 0 + h16;           sb = 16 + h16;          break;
            case 1: sa = 32 + h16;          sb = 48 + h16;          break;
            case 2: sa = 64 + b * 8 + h8;   sb = 96 + b * 8 + h8;   break;
            case 3: sa = 128 + b * 8 + h8;  sb = 160 + b * 8 + h8;  break;
            default: sa = 192 + b * 8 + h8; sb = -1;                break;
        }
        atomicAdd(&g_acc[sa], (double)va);
        if (sb >= 0) atomicAdd(&g_acc[sb], (double)vb);
    }

    // packed tap weights (built late: not live through phases 0-1)
    const float GW[6] = { 0.00102838f, 0.00759876f, 0.03600077f,
                          0.10936068f, 0.21300553f, 0.26601172f };
    ull W2[6];
    #pragma unroll
    for (int j = 0; j < 6; ++j) PACKF2(W2[j], GW[j], GW[j]);

    // ---- phase 2: horizontal 11-tap pass; 592 items x 4 outputs (77% fill)
    for (int it = tid; it < HALO_H * 8; it += 256) {
        const int r = it % HALO_H;         // r-major lanes -> conflict-free LDS
        const int g = it / HALO_H;         // 0..7
        const __half2* row = &sPT[r * SP_STRIDE + 4 * g];
        ull accPT[4], accSQ[4];
        #pragma unroll
        for (int o = 0; o < 4; ++o) { accPT[o] = 0ull; accSQ[o] = 0ull; }
        #pragma unroll
        for (int m = 0; m < 14; ++m) {
            const float2 f = __half22float2(row[m]);
            ull pt2; PACKF2(pt2, f.x, f.y);
            const float q_ = f.x * f.y;
            const float s_ = fmaf(f.x, f.x, f.y * f.y);
            ull sq2; PACKF2(sq2, s_, q_);
            #pragma unroll
            for (int o = 0; o < 4; ++o) {
                const int j = m - o;
                if (j >= 0 && j < 11) {
                    const int wi = (j < 6) ? j : 10 - j;
                    FMA2(accPT[o], W2[wi], pt2, accPT[o]);
                    FMA2(accSQ[o], W2[wi], sq2, accSQ[o]);
                }
            }
        }
        const int oi = r * H_STRIDE + 4 * g;
        #pragma unroll
        for (int o = 0; o < 4; ++o) {
            hPT[oi + o] = accPT[o];
            hSQ[oi + o] = accSQ[o];
        }
    }
    __syncthreads();

    // ---- phase 3: vertical pass + SSIM; each thread owns an 8-tall strip
    float a_ssim = 0.f;
    {
        const int x  = lane;
        const int yb = warp * 8;
        ull accM[8], accS[8];
        #pragma unroll
        for (int o = 0; o < 8; ++o) { accM[o] = 0ull; accS[o] = 0ull; }
        #pragma unroll
        for (int rr = 0; rr < 18; ++rr) {
            const int row = (yb + rr) * H_STRIDE + x;
            const ull vpt = hPT[row];
            const ull vsq = hSQ[row];
            #pragma unroll
            for (int o = 0; o < 8; ++o) {
                const int j = rr - o;
                if (j >= 0 && j < 11) {
                    const int wi = (j < 6) ? j : 10 - j;
                    FMA2(accM[o], W2[wi], vpt, accM[o]);
                    FMA2(accS[o], W2[wi], vsq, accS[o]);
                }
            }
        }
        #pragma unroll
        for (int o = 0; o < 8; ++o) {
            const int oy = y0 + yb + o, ox = x0 + x;
            if (oy < OUTHW && ox < OUTHW) {
                float m1, m2, css, csq;
                UNPACKF2(m1, m2, accM[o]);
                UNPACKF2(css, csq, accS[o]);
                const float m1s = m1 * m1, m2s = m2 * m2, m12 = m1 * m2;
                const float sigsum = css - m1s - m2s;
                const float sig12  = csq - m12;
                const float num = (2.f * m12 + C1V) * (2.f * sig12 + C2V);
                const float den = (m1s + m2s + C1V) * (sigsum + C2V);
                a_ssim += __fdividef(num, den);
            }
        }
    }

    // ---- ssim reduction
    #pragma unroll
    for (int o = 16; o; o >>= 1) a_ssim += __shfl_down_sync(0xffffffffu, a_ssim, o);
    if (lane == 0) redf[warp] = a_ssim;
    __syncthreads();
    if (warp == 0) {
        float v = (lane < 8) ? redf[lane] : 0.f;
        #pragma unroll
        for (int o = 4; o; o >>= 1) v += __shfl_down_sync(0xffffffffu, v, o);
        if (lane == 0)
            atomicAdd(&g_acc[224 + ((blockIdx.x + blockIdx.y) & 31)], (double)v);
    }

    // ---- last-block finalize (ticket; saves the separate kernel launch)
    __threadfence();
    if (tid == 0) s_ticket = atomicAdd(&g_ticket, 1u);
    __syncthreads();
    if (s_ticket != TOTAL_BLOCKS - 1) return;

    double* fs  = (double*)smraw;          // 256 doubles (all prior smem dead)
    double* fg2 = (double*)(smraw + 2048); // 32
    double* fpr = (double*)(smraw + 2304); // 12
    fs[tid] = __ldcg(&g_acc[tid]);
    __syncthreads();
    g_acc[tid] = 0.0;
    if (tid == 0) g_ticket = 0u;

    if (tid < 32) {
        const int bs = (tid < 24) ? (64 + 8 * tid) : (8 * (tid - 24));
        double v = 0.0;
        #pragma unroll
        for (int i = 0; i < 8; ++i) v += fs[bs + i];
        fg2[tid] = v;
    }
    __syncthreads();

    const double n = (double)NPIX;
    if (tid < 4) {
        const double sp  = fg2[tid],      st  = fg2[4 + tid];
        const double spp = fg2[8 + tid],  stt = fg2[12 + tid];
        const double mse = fg2[16 + tid] / n;
        const double pm = sp / n, tm = st / n;
        fpr[tid] = (pm - tm) * (pm - tm);
        const double vp = (spp - sp * sp / n) / (n - 1.0);
        const double vt = (stt - st * st / n) / (n - 1.0);
        const double ps = sqrt(fmax(vp, 0.0));
        const double ts = sqrt(fmax(vt, 0.0));
        fpr[4 + tid] = (ps - ts) * (ps - ts);
        fpr[8 + tid] = (mse == 0.0) ? 100.0 : 10.0 * log10(65025.0 / mse);
    }
    __syncthreads();

    if (tid == 0) {
        const double l1  = (fg2[24] + fg2[25]) / (4.0 * n);
        const double gcnt = 4.0 * 2047.0 * 2048.0;
        const double grad = (fg2[26] + fg2[27]) / gcnt + (fg2[28] + fg2[29]) / gcnt;
        const double rng = (fg2[30] + fg2[31]) / (4.0 * n);

        const double energy = 0.25 * (fpr[0] + fpr[1] + fpr[2] + fpr[3]);
        const double dist   = 0.25 * (fpr[4] + fpr[5] + fpr[6] + fpr[7]);
        const double psnr   = 0.25 * (fpr[8] + fpr[9] + fpr[10] + fpr[11]);
        const double phys = energy + 0.5 * dist + 0.1 * rng;

        const double ss = fg2[20] + fg2[21] + fg2[22] + fg2[23];
        double ssim_mean = ss / (4.0 * (double)OUTHW * (double)OUTHW);
        ssim_mean = fmin(fmax(ssim_mean, 0.0), 1.0);

        const double total = l1 + 0.15 * grad + 0.05 * phys + 0.1 * (1.0 - ssim_mean);
        out[0] = (float)total;
        out[1] = (float)psnr;
        out[2] = (float)ssim_mean;
    }
}

// ---------------------------------------------------------------------------
extern "C" void kernel_launch(void* const* d_in, const int* in_sizes, int n_in,
                              void* d_out, int out_size)
{
    const float* pred = (const float*)d_in[0];
    const float* tgt  = (const float*)d_in[1];
    float* out = (float*)d_out;

    cudaFuncSetAttribute(main_kernel,
                         cudaFuncAttributeMaxDynamicSharedMemorySize, SMEM_BYTES);
    dim3 g(IMG_W / TILE_W, IMG_H / TILE_H, NIMG);   // 64 x 32 x 4 = 8192
    main_kernel<<<g, 256, SMEM_BYTES>>>(pred, tgt, out);
}

// round 10
// speedup vs baseline: 1.6420x; 1.6420x over previous
#include <cuda_runtime.h>
#include <cuda_fp16.h>
#include <math.h>

#define IMG_H 2048
#define IMG_W 2048
#define NIMG  4
#define NPIX  (IMG_H * IMG_W)
#define OUTHW 2038                 /* 2048 - 11 + 1 */

#define C1V 6.5025f
#define C2V 58.5225f

#define TILE_W 32
#define TILE_H 64
#define HALO_H (TILE_H + 10)       /* 74 */
#define SP_STRIDE 49               /* half2 units; bank step 17 (odd) -> conflict-free */
#define H_STRIDE  33               /* ull units */

typedef unsigned long long ull;

/* dynamic smem layout (bytes) */
#define OFF_SPT 0                                  /* half2[74*49] = 14504 B */
#define OFF_HPT 14504                              /* ull  [74*33] = 19536 B */
#define OFF_HSQ (14504 + 19536)                    /* ull  [74*33] = 19536 B */
#define SMEM_BYTES (OFF_HSQ + 19536)               /* 53576 -> 4 blocks/SM   */

#define PACKF2(out, lo, hi) \
    asm("mov.b64 %0, {%1, %2};" : "=l"(out) : "f"(lo), "f"(hi))
#define UNPACKF2(lo, hi, in) \
    asm("mov.b64 {%0, %1}, %2;" : "=f"(lo), "=f"(hi) : "l"(in))
#define FMA2(d, a, b, c) \
    asm("fma.rn.f32x2 %0, %1, %2, %3;" : "=l"(d) : "l"(a), "l"(b), "l"(c))
#define ADD2(d, a, b) \
    asm("add.rn.f32x2 %0, %1, %2;" : "=l"(d) : "l"(a), "l"(b))

// accumulator slots (doubles), hashed:
//   [0..15] l1  [16..31] gx  [32..47] gy  [48..63] range
//   [64..95] sum_p[b][h8]  [96..127] sum_t  [128..159] sumsq_p
//   [160..191] sumsq_t  [192..223] mse8  [224..255] ssim
__device__ double g_acc[256];

__device__ __forceinline__ float quant_u8(float x) {
    return floorf(__saturatef((x + 1.0f) * 0.5f) * 255.0f);
}

// ---------------------------------------------------------------------------
__global__ __launch_bounds__(256, 4) void main_kernel(
    const float* __restrict__ pred, const float* __restrict__ tgt)
{
    extern __shared__ unsigned char smraw[];
    __half2* sPT = (__half2*)(smraw + OFF_SPT);
    ull*     hPT = (ull*)(smraw + OFF_HPT);
    ull*     hSQ = (ull*)(smraw + OFF_HSQ);
    float*   sD  = (float*)(smraw + OFF_HPT);  // alias: 65x34 d-values, dead before hPT written
    __shared__ ull  redu[8][5];
    __shared__ float redf[8];

    const int tid = threadIdx.x;
    const int lane = tid & 31, warp = tid >> 5;
    const int x0 = blockIdx.x * TILE_W;
    const int y0 = blockIdx.y * TILE_H;
    const int b  = blockIdx.z;
    const size_t base = (size_t)b * NPIX;
    const int h16 = (blockIdx.x + blockIdx.y) & 15;
    const int h8  = (blockIdx.x + blockIdx.y) & 7;

    float a_l1 = 0.f, a_gx = 0.f, a_gy = 0.f, a_rng = 0.f;
    float a_sp = 0.f, a_st = 0.f, a_spp = 0.f, a_stt = 0.f, a_mse = 0.f;

    // ---- phase 0a: interior (64 rows x 8 quads = 512 float4 items, 2/thread):
    //      unconditional stats + stores
    #pragma unroll
    for (int k = 0; k < 2; ++k) {
        const int i = tid + k * 256;            // 0..511
        const int r = i >> 3, q = i & 7;        // r 0..63, q 0..7
        const size_t off = base + (size_t)(y0 + r) * IMG_W + (x0 + 4 * q);
        const float4 p4 = *(const float4*)(pred + off);
        const float4 t4 = *(const float4*)(tgt  + off);
        const float pe[4] = { p4.x, p4.y, p4.z, p4.w };
        const float te[4] = { t4.x, t4.y, t4.z, t4.w };
        #pragma unroll
        for (int e = 0; e < 4; ++e) {
            const float p = pe[e], t = te[e];
            const float qp = quant_u8(p), qt = quant_u8(t);
            const int c = 4 * q + e;
            sPT[r * SP_STRIDE + c] = __floats2half2_rn(qp, qt);
            const float d = p - t;
            sD[r * 34 + c] = d;                 // r<64, c<32 always in range
            a_l1  += fabsf(d);
            a_rng += fmaxf(fabsf(p) - 1.f, 0.f);
            a_sp  += p;  a_st += t;
            a_spp = fmaf(p, p, a_spp);
            a_stt = fmaf(t, t, a_stt);
            const float qd = qp - qt;
            a_mse = fmaf(qd, qd, a_mse);
        }
    }

    // ---- phase 0b: halo only (rows 64..73 full width; cols 32..43 of rows 0..63)
    for (int i2 = tid; i2 < 302; i2 += 256) {
        int r, q;
        if (i2 < 110) { const int rr = i2 / 11; r = 64 + rr; q = i2 - rr * 11; }
        else          { const int j = i2 - 110; const int jr = j / 3; r = jr; q = 8 + (j - 3 * jr); }
        const int gy_ = y0 + r, cb = x0 + 4 * q;
        float4 p4 = make_float4(0.f, 0.f, 0.f, 0.f);
        float4 t4 = make_float4(0.f, 0.f, 0.f, 0.f);
        if (gy_ < IMG_H && cb < IMG_W) {
            const size_t off = base + (size_t)gy_ * IMG_W + cb;
            p4 = *(const float4*)(pred + off);
            t4 = *(const float4*)(tgt  + off);
        }
        const float pe[4] = { p4.x, p4.y, p4.z, p4.w };
        const float te[4] = { t4.x, t4.y, t4.z, t4.w };
        #pragma unroll
        for (int e = 0; e < 4; ++e) {
            const float p = pe[e], t = te[e];
            const int c = 4 * q + e;
            sPT[r * SP_STRIDE + c] = __floats2half2_rn(quant_u8(p), quant_u8(t));
            if (r < 65 && c < 34) sD[r * 34 + c] = p - t;   // bottom row 64 / cols 32,33
        }
    }
    __syncthreads();

    // ---- phase 1: gradient stats (2 pixels per iter, float2 loads; proven in R4)
    for (int i = tid; i < 1024; i += 256) {
        const int r = i >> 4, c2 = (i & 15) * 2;
        const float2 d01 = *(const float2*)&sD[r * 34 + c2];
        const float2 b01 = *(const float2*)&sD[(r + 1) * 34 + c2];
        const float d2 = sD[r * 34 + c2 + 2];
        if (y0 + r < IMG_H - 1) a_gx += fabsf(d01.x - b01.x) + fabsf(d01.y - b01.y);
        a_gy += fabsf(d01.x - d01.y);
        if (x0 + c2 + 1 < IMG_W - 1) a_gy += fabsf(d01.y - d2);
    }

    // ---- flush the 9 pointwise stats (frees registers for conv phases)
    {
        ull v[5];
        PACKF2(v[0], a_l1, a_gx);
        PACKF2(v[1], a_gy, a_rng);
        PACKF2(v[2], a_sp, a_st);
        PACKF2(v[3], a_spp, a_stt);
        PACKF2(v[4], a_mse, 0.f);
        #pragma unroll
        for (int i = 0; i < 5; ++i) {
            #pragma unroll
            for (int o = 16; o; o >>= 1) {
                ull t2 = __shfl_down_sync(0xffffffffu, v[i], o);
                ADD2(v[i], v[i], t2);
            }
            if (lane == 0) redu[warp][i] = v[i];
        }
    }
    __syncthreads();     // sD reads done -> hPT/hSQ writable; redu published
    if (warp == 0 && lane < 5) {
        ull s2 = redu[0][lane];
        #pragma unroll
        for (int w2 = 1; w2 < 8; ++w2) ADD2(s2, s2, redu[w2][lane]);
        float va, vb; UNPACKF2(va, vb, s2);
        int sa, sb;
        switch (lane) {
            case 0: sa = 0 + h16;           sb = 16 + h16;          break;
            case 1: sa = 32 + h16;          sb = 48 + h16;          break;
            case 2: sa = 64 + b * 8 + h8;   sb = 96 + b * 8 + h8;   break;
            case 3: sa = 128 + b * 8 + h8;  sb = 160 + b * 8 + h8;  break;
            default: sa = 192 + b * 8 + h8; sb = -1;                break;
        }
        atomicAdd(&g_acc[sa], (double)va);
        if (sb >= 0) atomicAdd(&g_acc[sb], (double)vb);
    }

    // packed tap weights (built late: not live through phases 0-1)
    const float GW[6] = { 0.00102838f, 0.00759876f, 0.03600077f,
                          0.10936068f, 0.21300553f, 0.26601172f };
    ull W2[6];
    #pragma unroll
    for (int j = 0; j < 6; ++j) PACKF2(W2[j], GW[j], GW[j]);

    // ---- phase 2: horizontal 11-tap pass; 592 items x 4 outputs (77% fill)
    for (int it = tid; it < HALO_H * 8; it += 256) {
        const int r = it % HALO_H;         // r-major lanes -> conflict-free LDS
        const int g = it / HALO_H;         // 0..7
        const __half2* row = &sPT[r * SP_STRIDE + 4 * g];
        ull accPT[4], accSQ[4];
        #pragma unroll
        for (int o = 0; o < 4; ++o) { accPT[o] = 0ull; accSQ[o] = 0ull; }
        #pragma unroll
        for (int m = 0; m < 14; ++m) {
            const float2 f = __half22float2(row[m]);
            ull pt2; PACKF2(pt2, f.x, f.y);
            const float q_ = f.x * f.y;
            const float s_ = fmaf(f.x, f.x, f.y * f.y);
            ull sq2; PACKF2(sq2, s_, q_);
            #pragma unroll
            for (int o = 0; o < 4; ++o) {
                const int j = m - o;
                if (j >= 0 && j < 11) {
                    const int wi = (j < 6) ? j : 10 - j;
                    FMA2(accPT[o], W2[wi], pt2, accPT[o]);
                    FMA2(accSQ[o], W2[wi], sq2, accSQ[o]);
                }
            }
        }
        const int oi = r * H_STRIDE + 4 * g;
        #pragma unroll
        for (int o = 0; o < 4; ++o) {
            hPT[oi + o] = accPT[o];
            hSQ[oi + o] = accSQ[o];
        }
    }
    __syncthreads();

    // ---- phase 3: vertical pass + SSIM; each thread owns an 8-tall strip
    float a_ssim = 0.f;
    {
        const int x  = lane;
        const int yb = warp * 8;
        ull accM[8], accS[8];
        #pragma unroll
        for (int o = 0; o < 8; ++o) { accM[o] = 0ull; accS[o] = 0ull; }
        #pragma unroll
        for (int rr = 0; rr < 18; ++rr) {
            const int row = (yb + rr) * H_STRIDE + x;
            const ull vpt = hPT[row];
            const ull vsq = hSQ[row];
            #pragma unroll
            for (int o = 0; o < 8; ++o) {
                const int j = rr - o;
                if (j >= 0 && j < 11) {
                    const int wi = (j < 6) ? j : 10 - j;
                    FMA2(accM[o], W2[wi], vpt, accM[o]);
                    FMA2(accS[o], W2[wi], vsq, accS[o]);
                }
            }
        }
        #pragma unroll
        for (int o = 0; o < 8; ++o) {
            const int oy = y0 + yb + o, ox = x0 + x;
            if (oy < OUTHW && ox < OUTHW) {
                float m1, m2, css, csq;
                UNPACKF2(m1, m2, accM[o]);
                UNPACKF2(css, csq, accS[o]);
                const float m1s = m1 * m1, m2s = m2 * m2, m12 = m1 * m2;
                const float sigsum = css - m1s - m2s;
                const float sig12  = csq - m12;
                const float num = (2.f * m12 + C1V) * (2.f * sig12 + C2V);
                const float den = (m1s + m2s + C1V) * (sigsum + C2V);
                a_ssim += __fdividef(num, den);
            }
        }
    }

    // ---- ssim reduction
    #pragma unroll
    for (int o = 16; o; o >>= 1) a_ssim += __shfl_down_sync(0xffffffffu, a_ssim, o);
    if (lane == 0) redf[warp] = a_ssim;
    __syncthreads();
    if (warp == 0) {
        float v = (lane < 8) ? redf[lane] : 0.f;
        #pragma unroll
        for (int o = 4; o; o >>= 1) v += __shfl_down_sync(0xffffffffu, v, o);
        if (lane == 0)
            atomicAdd(&g_acc[224 + ((blockIdx.x + blockIdx.y) & 31)], (double)v);
    }
}

// ---------------------------------------------------------------------------
// Parallel finalize: group sums in 32 lanes, per-image sqrt/log10 in 4 lanes,
// thread 0 combines. g_acc re-zeroed for the next replay.
// ---------------------------------------------------------------------------
__global__ __launch_bounds__(256) void finalize_kernel(float* __restrict__ out)
{
    __shared__ double s[256];
    __shared__ double g2[32];
    __shared__ double per[12];
    const int t = threadIdx.x;
    s[t] = g_acc[t];
    __syncthreads();
    g_acc[t] = 0.0;

    if (t < 32) {
        const int bs = (t < 24) ? (64 + 8 * t) : (8 * (t - 24));
        double v = 0.0;
        #pragma unroll
        for (int i = 0; i < 8; ++i) v += s[bs + i];
        g2[t] = v;
    }
    __syncthreads();

    const double n = (double)NPIX;
    if (t < 4) {
        const double sp  = g2[t],      st  = g2[4 + t];
        const double spp = g2[8 + t],  stt = g2[12 + t];
        const double mse = g2[16 + t] / n;
        const double pm = sp / n, tm = st / n;
        per[t] = (pm - tm) * (pm - tm);
        const double vp = (spp - sp * sp / n) / (n - 1.0);
        const double vt = (stt - st * st / n) / (n - 1.0);
        const double ps = sqrt(fmax(vp, 0.0));
        const double ts = sqrt(fmax(vt, 0.0));
        per[4 + t] = (ps - ts) * (ps - ts);
        per[8 + t] = (mse == 0.0) ? 100.0 : 10.0 * log10(65025.0 / mse);
    }
    __syncthreads();

    if (t == 0) {
        const double l1  = (g2[24] + g2[25]) / (4.0 * n);
        const double gcnt = 4.0 * 2047.0 * 2048.0;
        const double grad = (g2[26] + g2[27]) / gcnt + (g2[28] + g2[29]) / gcnt;
        const double rng = (g2[30] + g2[31]) / (4.0 * n);

        const double energy = 0.25 * (per[0] + per[1] + per[2] + per[3]);
        const double dist   = 0.25 * (per[4] + per[5] + per[6] + per[7]);
        const double psnr   = 0.25 * (per[8] + per[9] + per[10] + per[11]);
        const double phys = energy + 0.5 * dist + 0.1 * rng;

        const double ss = g2[20] + g2[21] + g2[22] + g2[23];
        double ssim_mean = ss / (4.0 * (double)OUTHW * (double)OUTHW);
        ssim_mean = fmin(fmax(ssim_mean, 0.0), 1.0);

        const double total = l1 + 0.15 * grad + 0.05 * phys + 0.1 * (1.0 - ssim_mean);
        out[0] = (float)total;
        out[1] = (float)psnr;
        out[2] = (float)ssim_mean;
    }
}

// ---------------------------------------------------------------------------
extern "C" void kernel_launch(void* const* d_in, const int* in_sizes, int n_in,
                              void* d_out, int out_size)
{
    const float* pred = (const float*)d_in[0];
    const float* tgt  = (const float*)d_in[1];
    float* out = (float*)d_out;

    cudaFuncSetAttribute(main_kernel,
                         cudaFuncAttributeMaxDynamicSharedMemorySize, SMEM_BYTES);
    dim3 g(IMG_W / TILE_W, IMG_H / TILE_H, NIMG);   // 64 x 32 x 4 = 8192
    main_kernel<<<g, 256, SMEM_BYTES>>>(pred, tgt);
    finalize_kernel<<<1, 256>>>(out);
}

// round 14
// speedup vs baseline: 1.6543x; 1.0074x over previous
#include <cuda_runtime.h>
#include <cuda_fp16.h>
#include <math.h>

#define IMG_H 2048
#define IMG_W 2048
#define NIMG  4
#define NPIX  (IMG_H * IMG_W)
#define OUTHW 2038                 /* 2048 - 11 + 1 */

#define C1V 6.5025f
#define C2V 58.5225f

#define TILE_W 32
#define TILE_H 64
#define HALO_H (TILE_H + 10)       /* 74 */
#define SP_STRIDE 49               /* half2 units; bank step 17 (odd) -> conflict-free */
#define H_STRIDE  33               /* float4 units; 33 mod 8 = 1 -> conflict-free */

typedef unsigned long long ull;

/* dynamic smem layout (bytes) */
#define OFF_SPT 0                                  /* half2 [74*49] = 14504 B  */
#define OFF_H   14512                              /* 16B-ALIGNED; float4[74*33] = 39072 B */
#define SMEM_BYTES (OFF_H + 39072)                 /* 53584 -> 4 blocks/SM     */

#define PACKF2(out, lo, hi) \
    asm("mov.b64 %0, {%1, %2};" : "=l"(out) : "f"(lo), "f"(hi))
#define UNPACKF2(lo, hi, in) \
    asm("mov.b64 {%0, %1}, %2;" : "=f"(lo), "=f"(hi) : "l"(in))
#define FMA2(d, a, b, c) \
    asm("fma.rn.f32x2 %0, %1, %2, %3;" : "=l"(d) : "l"(a), "l"(b), "l"(c))
#define ADD2(d, a, b) \
    asm("add.rn.f32x2 %0, %1, %2;" : "=l"(d) : "l"(a), "l"(b))

// accumulator slots (doubles), hashed:
//   [0..15] l1  [16..31] gx  [32..47] gy  [48..63] range
//   [64..95] sum_p[b][h8]  [96..127] sum_t  [128..159] sumsq_p
//   [160..191] sumsq_t  [192..223] mse8  [224..255] ssim
__device__ double g_acc[256];

__device__ __forceinline__ float quant_u8(float x) {
    return floorf(__saturatef((x + 1.0f) * 0.5f) * 255.0f);
}

// ---------------------------------------------------------------------------
__global__ __launch_bounds__(256, 4) void main_kernel(
    const float* __restrict__ pred, const float* __restrict__ tgt)
{
    extern __shared__ unsigned char smraw[];
    __half2* sPT = (__half2*)(smraw + OFF_SPT);
    float4*  h4  = (float4*)(smraw + OFF_H);
    float*   sD  = (float*)(smraw + OFF_H);    // alias: 65x34 d-values, dead before h4 written
    __shared__ ull  redu[8][5];
    __shared__ float redf[8];

    const int tid = threadIdx.x;
    const int lane = tid & 31, warp = tid >> 5;
    const int x0 = blockIdx.x * TILE_W;
    const int y0 = blockIdx.y * TILE_H;
    const int b  = blockIdx.z;
    const size_t base = (size_t)b * NPIX;
    const int h16 = (blockIdx.x + blockIdx.y) & 15;
    const int h8  = (blockIdx.x + blockIdx.y) & 7;

    float a_l1 = 0.f, a_gx = 0.f, a_gy = 0.f, a_rng = 0.f;
    float a_sp = 0.f, a_st = 0.f, a_spp = 0.f, a_stt = 0.f, a_mse = 0.f;

    // ---- phase 0a: interior (64 rows x 8 quads = 512 float4 items, 2/thread):
    //      unconditional stats + stores
    #pragma unroll
    for (int k = 0; k < 2; ++k) {
        const int i = tid + k * 256;            // 0..511
        const int r = i >> 3, q = i & 7;        // r 0..63, q 0..7
        const size_t off = base + (size_t)(y0 + r) * IMG_W + (x0 + 4 * q);
        const float4 p4 = *(const float4*)(pred + off);
        const float4 t4 = *(const float4*)(tgt  + off);
        const float pe[4] = { p4.x, p4.y, p4.z, p4.w };
        const float te[4] = { t4.x, t4.y, t4.z, t4.w };
        #pragma unroll
        for (int e = 0; e < 4; ++e) {
            const float p = pe[e], t = te[e];
            const float qp = quant_u8(p), qt = quant_u8(t);
            const int c = 4 * q + e;
            sPT[r * SP_STRIDE + c] = __floats2half2_rn(qp, qt);
            const float d = p - t;
            sD[r * 34 + c] = d;                 // r<64, c<32 always in range
            a_l1  += fabsf(d);
            a_rng += fmaxf(fabsf(p) - 1.f, 0.f);
            a_sp  += p;  a_st += t;
            a_spp = fmaf(p, p, a_spp);
            a_stt = fmaf(t, t, a_stt);
            const float qd = qp - qt;
            a_mse = fmaf(qd, qd, a_mse);
        }
    }

    // ---- phase 0b: halo only (rows 64..73 full width; cols 32..43 of rows 0..63)
    for (int i2 = tid; i2 < 302; i2 += 256) {
        int r, q;
        if (i2 < 110) { const int rr = i2 / 11; r = 64 + rr; q = i2 - rr * 11; }
        else          { const int j = i2 - 110; const int jr = j / 3; r = jr; q = 8 + (j - 3 * jr); }
        const int gy_ = y0 + r, cb = x0 + 4 * q;
        float4 p4 = make_float4(0.f, 0.f, 0.f, 0.f);
        float4 t4 = make_float4(0.f, 0.f, 0.f, 0.f);
        if (gy_ < IMG_H && cb < IMG_W) {
            const size_t off = base + (size_t)gy_ * IMG_W + cb;
            p4 = *(const float4*)(pred + off);
            t4 = *(const float4*)(tgt  + off);
        }
        const float pe[4] = { p4.x, p4.y, p4.z, p4.w };
        const float te[4] = { t4.x, t4.y, t4.z, t4.w };
        #pragma unroll
        for (int e = 0; e < 4; ++e) {
            const float p = pe[e], t = te[e];
            const int c = 4 * q + e;
            sPT[r * SP_STRIDE + c] = __floats2half2_rn(quant_u8(p), quant_u8(t));
            if (r < 65 && c < 34) sD[r * 34 + c] = p - t;   // bottom row 64 / cols 32,33
        }
    }
    __syncthreads();

    // ---- phase 1: gradient stats (2 pixels per iter, float2 loads)
    for (int i = tid; i < 1024; i += 256) {
        const int r = i >> 4, c2 = (i & 15) * 2;
        const float2 d01 = *(const float2*)&sD[r * 34 + c2];
        const float2 b01 = *(const float2*)&sD[(r + 1) * 34 + c2];
        const float d2 = sD[r * 34 + c2 + 2];
        if (y0 + r < IMG_H - 1) a_gx += fabsf(d01.x - b01.x) + fabsf(d01.y - b01.y);
        a_gy += fabsf(d01.x - d01.y);
        if (x0 + c2 + 1 < IMG_W - 1) a_gy += fabsf(d01.y - d2);
    }

    // ---- flush the 9 pointwise stats (frees registers for conv phases)
    {
        ull v[5];
        PACKF2(v[0], a_l1, a_gx);
        PACKF2(v[1], a_gy, a_rng);
        PACKF2(v[2], a_sp, a_st);
        PACKF2(v[3], a_spp, a_stt);
        PACKF2(v[4], a_mse, 0.f);
        #pragma unroll
        for (int i = 0; i < 5; ++i) {
            #pragma unroll
            for (int o = 16; o; o >>= 1) {
                ull t2 = __shfl_down_sync(0xffffffffu, v[i], o);
                ADD2(v[i], v[i], t2);
            }
            if (lane == 0) redu[warp][i] = v[i];
        }
    }
    __syncthreads();     // sD reads done -> h4 writable; redu published
    if (warp == 0 && lane < 5) {
        ull s2 = redu[0][lane];
        #pragma unroll
        for (int w2 = 1; w2 < 8; ++w2) ADD2(s2, s2, redu[w2][lane]);
        float va, vb; UNPACKF2(va, vb, s2);
        int sa, sb;
        switch (lane) {
            case 0: sa = 0 + h16;           sb = 16 + h16;          break;
            case 1: sa = 32 + h16;          sb = 48 + h16;          break;
            case 2: sa = 64 + b * 8 + h8;   sb = 96 + b * 8 + h8;   break;
            case 3: sa = 128 + b * 8 + h8;  sb = 160 + b * 8 + h8;  break;
            default: sa = 192 + b * 8 + h8; sb = -1;                break;
        }
        atomicAdd(&g_acc[sa], (double)va);
        if (sb >= 0) atomicAdd(&g_acc[sb], (double)vb);
    }

    // packed tap weights (built late: not live through phases 0-1)
    const float GW[6] = { 0.00102838f, 0.00759876f, 0.03600077f,
                          0.10936068f, 0.21300553f, 0.26601172f };
    ull W2[6];
    #pragma unroll
    for (int j = 0; j < 6; ++j) PACKF2(W2[j], GW[j], GW[j]);

    // ---- phase 2: horizontal 11-tap pass; 592 items x 4 outputs (77% fill)
    for (int it = tid; it < HALO_H * 8; it += 256) {
        const int r = it % HALO_H;         // r-major lanes -> conflict-free LDS/STS
        const int g = it / HALO_H;         // 0..7
        const __half2* row = &sPT[r * SP_STRIDE + 4 * g];
        ull accPT[4], accSQ[4];
        #pragma unroll
        for (int o = 0; o < 4; ++o) { accPT[o] = 0ull; accSQ[o] = 0ull; }
        #pragma unroll
        for (int m = 0; m < 14; ++m) {
            const float2 f = __half22float2(row[m]);
            ull pt2; PACKF2(pt2, f.x, f.y);
            const float q_ = f.x * f.y;
            const float s_ = fmaf(f.x, f.x, f.y * f.y);
            ull sq2; PACKF2(sq2, s_, q_);
            #pragma unroll
            for (int o = 0; o < 4; ++o) {
                const int j = m - o;
                if (j >= 0 && j < 11) {
                    const int wi = (j < 6) ? j : 10 - j;
                    FMA2(accPT[o], W2[wi], pt2, accPT[o]);
                    FMA2(accSQ[o], W2[wi], sq2, accSQ[o]);
                }
            }
        }
        const int oi = r * H_STRIDE + 4 * g;
        #pragma unroll
        for (int o = 0; o < 4; ++o) {
            float hp_, ht_, hs_, hq_;
            UNPACKF2(hp_, ht_, accPT[o]);
            UNPACKF2(hs_, hq_, accSQ[o]);
            h4[oi + o] = make_float4(hp_, ht_, hs_, hq_);   // one STS.128
        }
    }
    __syncthreads();

    // ---- phase 3: vertical pass + SSIM; each thread owns an 8-tall strip
    float a_ssim = 0.f;
    {
        const int x  = lane;
        const int yb = warp * 8;
        ull accM[8], accS[8];
        #pragma unroll
        for (int o = 0; o < 8; ++o) { accM[o] = 0ull; accS[o] = 0ull; }
        #pragma unroll
        for (int rr = 0; rr < 18; ++rr) {
            const float4 v = h4[(yb + rr) * H_STRIDE + x];  // one LDS.128
            ull vpt, vsq;
            PACKF2(vpt, v.x, v.y);
            PACKF2(vsq, v.z, v.w);
            #pragma unroll
            for (int o = 0; o < 8; ++o) {
                const int j = rr - o;
                if (j >= 0 && j < 11) {
                    const int wi = (j < 6) ? j : 10 - j;
                    FMA2(accM[o], W2[wi], vpt, accM[o]);
                    FMA2(accS[o], W2[wi], vsq, accS[o]);
                }
            }
        }
        #pragma unroll
        for (int o = 0; o < 8; ++o) {
            const int oy = y0 + yb + o, ox = x0 + x;
            if (oy < OUTHW && ox < OUTHW) {
                float m1, m2, css, csq;
                UNPACKF2(m1, m2, accM[o]);
                UNPACKF2(css, csq, accS[o]);
                const float m1s = m1 * m1, m2s = m2 * m2, m12 = m1 * m2;
                const float sigsum = css - m1s - m2s;
                const float sig12  = csq - m12;
                const float num = (2.f * m12 + C1V) * (2.f * sig12 + C2V);
                const float den = (m1s + m2s + C1V) * (sigsum + C2V);
                a_ssim += __fdividef(num, den);
            }
        }
    }

    // ---- ssim reduction
    #pragma unroll
    for (int o = 16; o; o >>= 1) a_ssim += __shfl_down_sync(0xffffffffu, a_ssim, o);
    if (lane == 0) redf[warp] = a_ssim;
    __syncthreads();
    if (warp == 0) {
        float v = (lane < 8) ? redf[lane] : 0.f;
        #pragma unroll
        for (int o = 4; o; o >>= 1) v += __shfl_down_sync(0xffffffffu, v, o);
        if (lane == 0)
            atomicAdd(&g_acc[224 + ((blockIdx.x + blockIdx.y) & 31)], (double)v);
    }
}

// ---------------------------------------------------------------------------
// Parallel finalize, PDL-launched: grid dependency sync replaces the serial
// launch gap. g_acc re-zeroed for the next replay.
// ---------------------------------------------------------------------------
__global__ __launch_bounds__(256) void finalize_kernel(float* __restrict__ out)
{
#if __CUDA_ARCH__ >= 900
    cudaGridDependencySynchronize();
#endif
    __shared__ double s[256];
    __shared__ double g2[32];
    __shared__ double per[12];
    const int t = threadIdx.x;
    s[t] = g_acc[t];
    __syncthreads();
    g_acc[t] = 0.0;

    if (t < 32) {
        const int bs = (t < 24) ? (64 + 8 * t) : (8 * (t - 24));
        double v = 0.0;
        #pragma unroll
        for (int i = 0; i < 8; ++i) v += s[bs + i];
        g2[t] = v;
    }
    __syncthreads();

    const double n = (double)NPIX;
    if (t < 4) {
        const double sp  = g2[t],      st  = g2[4 + t];
        const double spp = g2[8 + t],  stt = g2[12 + t];
        const double mse = g2[16 + t] / n;
        const double pm = sp / n, tm = st / n;
        per[t] = (pm - tm) * (pm - tm);
        const double vp = (spp - sp * sp / n) / (n - 1.0);
        const double vt = (stt - st * st / n) / (n - 1.0);
        const double ps = sqrt(fmax(vp, 0.0));
        const double ts = sqrt(fmax(vt, 0.0));
        per[4 + t] = (ps - ts) * (ps - ts);
        per[8 + t] = (mse == 0.0) ? 100.0 : 10.0 * log10(65025.0 / mse);
    }
    __syncthreads();

    if (t == 0) {
        const double l1  = (g2[24] + g2[25]) / (4.0 * n);
        const double gcnt = 4.0 * 2047.0 * 2048.0;
        const double grad = (g2[26] + g2[27]) / gcnt + (g2[28] + g2[29]) / gcnt;
        const double rng = (g2[30] + g2[31]) / (4.0 * n);

        const double energy = 0.25 * (per[0] + per[1] + per[2] + per[3]);
        const double dist   = 0.25 * (per[4] + per[5] + per[6] + per[7]);
        const double psnr   = 0.25 * (per[8] + per[9] + per[10] + per[11]);
        const double phys = energy + 0.5 * dist + 0.1 * rng;

        const double ss = g2[20] + g2[21] + g2[22] + g2[23];
        double ssim_mean = ss / (4.0 * (double)OUTHW * (double)OUTHW);
        ssim_mean = fmin(fmax(ssim_mean, 0.0), 1.0);

        const double total = l1 + 0.15 * grad + 0.05 * phys + 0.1 * (1.0 - ssim_mean);
        out[0] = (float)total;
        out[1] = (float)psnr;
        out[2] = (float)ssim_mean;
    }
}

// ---------------------------------------------------------------------------
extern "C" void kernel_launch(void* const* d_in, const int* in_sizes, int n_in,
                              void* d_out, int out_size)
{
    const float* pred = (const float*)d_in[0];
    const float* tgt  = (const float*)d_in[1];
    float* out = (float*)d_out;

    cudaFuncSetAttribute(main_kernel,
                         cudaFuncAttributeMaxDynamicSharedMemorySize, SMEM_BYTES);
    dim3 g(IMG_W / TILE_W, IMG_H / TILE_H, NIMG);   // 64 x 32 x 4 = 8192
    main_kernel<<<g, 256, SMEM_BYTES>>>(pred, tgt);

    // PDL: overlap finalize's launch latency with the main kernel tail.
    cudaLaunchConfig_t cfg = {};
    cfg.gridDim = dim3(1, 1, 1);
    cfg.blockDim = dim3(256, 1, 1);
    cfg.dynamicSmemBytes = 0;
    cfg.stream = 0;
    cudaLaunchAttribute attrs[1];
    attrs[0].id = cudaLaunchAttributeProgrammaticStreamSerialization;
    attrs[0].val.programmaticStreamSerializationAllowed = 1;
    cfg.attrs = attrs;
    cfg.numAttrs = 1;
    cudaLaunchKernelEx(&cfg, finalize_kernel, out);
}

// round 15
// speedup vs baseline: 1.6962x; 1.0253x over previous
#include <cuda_runtime.h>
#include <cuda_fp16.h>
#include <math.h>

#define IMG_H 2048
#define IMG_W 2048
#define NIMG  4
#define NPIX  (IMG_H * IMG_W)
#define OUTHW 2038                 /* 2048 - 11 + 1 */

#define C1V 6.5025f
#define C2V 58.5225f

#define TILE_W 32
#define TILE_H 64
#define HALO_H (TILE_H + 10)       /* 74 */
#define SP_STRIDE 49               /* half2 units; bank step 17 (odd) -> conflict-free */
#define H_STRIDE  33               /* float4 units; 33 mod 8 = 1 -> conflict-free */

typedef unsigned long long ull;

/* dynamic smem layout (bytes) */
#define OFF_SPT 0                                  /* half2 [74*49] = 14504 B  */
#define OFF_H   14512                              /* 16B-ALIGNED; float4[74*33] = 39072 B */
#define SMEM_BYTES (OFF_H + 39072)                 /* 53584 -> 4 blocks/SM     */

#define PACKF2(out, lo, hi) \
    asm("mov.b64 %0, {%1, %2};" : "=l"(out) : "f"(lo), "f"(hi))
#define UNPACKF2(lo, hi, in) \
    asm("mov.b64 {%0, %1}, %2;" : "=f"(lo), "=f"(hi) : "l"(in))
#define FMA2(d, a, b, c) \
    asm("fma.rn.f32x2 %0, %1, %2, %3;" : "=l"(d) : "l"(a), "l"(b), "l"(c))
#define ADD2(d, a, b) \
    asm("add.rn.f32x2 %0, %1, %2;" : "=l"(d) : "l"(a), "l"(b))

// exact / near-exact reciprocal constants (n = 2^22)
#define INV_N    2.384185791015625e-07      /* 2^-22, exact */
#define INV_4N   5.9604644775390625e-08     /* 2^-24, exact */
#define INV_NM1  2.3841863594498458e-07     /* 1/(2^22-1), <=1ulp */
#define INV_GCNT 5.9633760368463204e-08     /* 1/(4*2047*2048), <=1ulp */
#define LOG10_65025F 4.8130803f

// accumulator slots (doubles), hashed:
//   [0..15] l1  [16..31] gx  [32..47] gy  [48..63] range
//   [64..95] sum_p[b][h8]  [96..127] sum_t  [128..159] sumsq_p
//   [160..191] sumsq_t  [192..223] mse8  [224..255] ssim
__device__ double g_acc[256];

__device__ __forceinline__ float quant_u8(float x) {
    return floorf(__saturatef((x + 1.0f) * 0.5f) * 255.0f);
}

// ---------------------------------------------------------------------------
__global__ __launch_bounds__(256, 4) void main_kernel(
    const float* __restrict__ pred, const float* __restrict__ tgt)
{
#if __CUDA_ARCH__ >= 900
    // Early trigger: finalize_kernel launches now and parks on its grid-dep
    // sync, so its launch setup fully overlaps this grid's execution.
    cudaTriggerProgrammaticLaunchCompletion();
#endif
    extern __shared__ unsigned char smraw[];
    __half2* sPT = (__half2*)(smraw + OFF_SPT);
    float4*  h4  = (float4*)(smraw + OFF_H);
    float*   sD  = (float*)(smraw + OFF_H);    // alias: 65x34 d-values, dead before h4 written
    __shared__ ull  redu[8][5];
    __shared__ float redf[8];

    const int tid = threadIdx.x;
    const int lane = tid & 31, warp = tid >> 5;
    const int x0 = blockIdx.x * TILE_W;
    const int y0 = blockIdx.y * TILE_H;
    const int b  = blockIdx.z;
    const size_t base = (size_t)b * NPIX;
    const int h16 = (blockIdx.x + blockIdx.y) & 15;
    const int h8  = (blockIdx.x + blockIdx.y) & 7;

    float a_l1 = 0.f, a_gx = 0.f, a_gy = 0.f, a_rng = 0.f;
    float a_sp = 0.f, a_st = 0.f, a_spp = 0.f, a_stt = 0.f, a_mse = 0.f;

    // ---- phase 0a: interior (64 rows x 8 quads = 512 float4 items, 2/thread):
    //      unconditional stats + stores
    #pragma unroll
    for (int k = 0; k < 2; ++k) {
        const int i = tid + k * 256;            // 0..511
        const int r = i >> 3, q = i & 7;        // r 0..63, q 0..7
        const size_t off = base + (size_t)(y0 + r) * IMG_W + (x0 + 4 * q);
        const float4 p4 = *(const float4*)(pred + off);
        const float4 t4 = *(const float4*)(tgt  + off);
        const float pe[4] = { p4.x, p4.y, p4.z, p4.w };
        const float te[4] = { t4.x, t4.y, t4.z, t4.w };
        #pragma unroll
        for (int e = 0; e < 4; ++e) {
            const float p = pe[e], t = te[e];
            const float qp = quant_u8(p), qt = quant_u8(t);
            const int c = 4 * q + e;
            sPT[r * SP_STRIDE + c] = __floats2half2_rn(qp, qt);
            const float d = p - t;
            sD[r * 34 + c] = d;                 // r<64, c<32 always in range
            a_l1  += fabsf(d);
            a_rng += fmaxf(fabsf(p) - 1.f, 0.f);
            a_sp  += p;  a_st += t;
            a_spp = fmaf(p, p, a_spp);
            a_stt = fmaf(t, t, a_stt);
            const float qd = qp - qt;
            a_mse = fmaf(qd, qd, a_mse);
        }
    }

    // ---- phase 0b: halo only (rows 64..73 full width; cols 32..43 of rows 0..63)
    for (int i2 = tid; i2 < 302; i2 += 256) {
        int r, q;
        if (i2 < 110) { const int rr = i2 / 11; r = 64 + rr; q = i2 - rr * 11; }
        else          { const int j = i2 - 110; const int jr = j / 3; r = jr; q = 8 + (j - 3 * jr); }
        const int gy_ = y0 + r, cb = x0 + 4 * q;
        float4 p4 = make_float4(0.f, 0.f, 0.f, 0.f);
        float4 t4 = make_float4(0.f, 0.f, 0.f, 0.f);
        if (gy_ < IMG_H && cb < IMG_W) {
            const size_t off = base + (size_t)gy_ * IMG_W + cb;
            p4 = *(const float4*)(pred + off);
            t4 = *(const float4*)(tgt  + off);
        }
        const float pe[4] = { p4.x, p4.y, p4.z, p4.w };
        const float te[4] = { t4.x, t4.y, t4.z, t4.w };
        #pragma unroll
        for (int e = 0; e < 4; ++e) {
            const float p = pe[e], t = te[e];
            const int c = 4 * q + e;
            sPT[r * SP_STRIDE + c] = __floats2half2_rn(quant_u8(p), quant_u8(t));
            if (r < 65 && c < 34) sD[r * 34 + c] = p - t;   // bottom row 64 / cols 32,33
        }
    }
    __syncthreads();

    // ---- phase 1: gradient stats (2 pixels per iter, float2 loads)
    for (int i = tid; i < 1024; i += 256) {
        const int r = i >> 4, c2 = (i & 15) * 2;
        const float2 d01 = *(const float2*)&sD[r * 34 + c2];
        const float2 b01 = *(const float2*)&sD[(r + 1) * 34 + c2];
        const float d2 = sD[r * 34 + c2 + 2];
        if (y0 + r < IMG_H - 1) a_gx += fabsf(d01.x - b01.x) + fabsf(d01.y - b01.y);
        a_gy += fabsf(d01.x - d01.y);
        if (x0 + c2 + 1 < IMG_W - 1) a_gy += fabsf(d01.y - d2);
    }

    // ---- flush the 9 pointwise stats (frees registers for conv phases)
    {
        ull v[5];
        PACKF2(v[0], a_l1, a_gx);
        PACKF2(v[1], a_gy, a_rng);
        PACKF2(v[2], a_sp, a_st);
        PACKF2(v[3], a_spp, a_stt);
        PACKF2(v[4], a_mse, 0.f);
        #pragma unroll
        for (int i = 0; i < 5; ++i) {
            #pragma unroll
            for (int o = 16; o; o >>= 1) {
                ull t2 = __shfl_down_sync(0xffffffffu, v[i], o);
                ADD2(v[i], v[i], t2);
            }
            if (lane == 0) redu[warp][i] = v[i];
        }
    }
    __syncthreads();     // sD reads done -> h4 writable; redu published
    if (warp == 0 && lane < 5) {
        ull s2 = redu[0][lane];
        #pragma unroll
        for (int w2 = 1; w2 < 8; ++w2) ADD2(s2, s2, redu[w2][lane]);
        float va, vb; UNPACKF2(va, vb, s2);
        int sa, sb;
        switch (lane) {
            case 0: sa = 0 + h16;           sb = 16 + h16;          break;
            case 1: sa = 32 + h16;          sb = 48 + h16;          break;
            case 2: sa = 64 + b * 8 + h8;   sb = 96 + b * 8 + h8;   break;
            case 3: sa = 128 + b * 8 + h8;  sb = 160 + b * 8 + h8;  break;
            default: sa = 192 + b * 8 + h8; sb = -1;                break;
        }
        atomicAdd(&g_acc[sa], (double)va);
        if (sb >= 0) atomicAdd(&g_acc[sb], (double)vb);
    }

    // packed tap weights (built late: not live through phases 0-1)
    const float GW[6] = { 0.00102838f, 0.00759876f, 0.03600077f,
                          0.10936068f, 0.21300553f, 0.26601172f };
    ull W2[6];
    #pragma unroll
    for (int j = 0; j < 6; ++j) PACKF2(W2[j], GW[j], GW[j]);

    // ---- phase 2: horizontal 11-tap pass; 592 items x 4 outputs (77% fill)
    for (int it = tid; it < HALO_H * 8; it += 256) {
        const int r = it % HALO_H;         // r-major lanes -> conflict-free LDS/STS
        const int g = it / HALO_H;         // 0..7
        const __half2* row = &sPT[r * SP_STRIDE + 4 * g];
        ull accPT[4], accSQ[4];
        #pragma unroll
        for (int o = 0; o < 4; ++o) { accPT[o] = 0ull; accSQ[o] = 0ull; }
        #pragma unroll
        for (int m = 0; m < 14; ++m) {
            const float2 f = __half22float2(row[m]);
            ull pt2; PACKF2(pt2, f.x, f.y);
            const float q_ = f.x * f.y;
            const float s_ = fmaf(f.x, f.x, f.y * f.y);
            ull sq2; PACKF2(sq2, s_, q_);
            #pragma unroll
            for (int o = 0; o < 4; ++o) {
                const int j = m - o;
                if (j >= 0 && j < 11) {
                    const int wi = (j < 6) ? j : 10 - j;
                    FMA2(accPT[o], W2[wi], pt2, accPT[o]);
                    FMA2(accSQ[o], W2[wi], sq2, accSQ[o]);
                }
            }
        }
        const int oi = r * H_STRIDE + 4 * g;
        #pragma unroll
        for (int o = 0; o < 4; ++o) {
            float hp_, ht_, hs_, hq_;
            UNPACKF2(hp_, ht_, accPT[o]);
            UNPACKF2(hs_, hq_, accSQ[o]);
            h4[oi + o] = make_float4(hp_, ht_, hs_, hq_);   // one STS.128
        }
    }
    __syncthreads();

    // ---- phase 3: vertical pass + SSIM; each thread owns an 8-tall strip
    float a_ssim = 0.f;
    {
        const int x  = lane;
        const int yb = warp * 8;
        ull accM[8], accS[8];
        #pragma unroll
        for (int o = 0; o < 8; ++o) { accM[o] = 0ull; accS[o] = 0ull; }
        #pragma unroll
        for (int rr = 0; rr < 18; ++rr) {
            const float4 v = h4[(yb + rr) * H_STRIDE + x];  // one LDS.128
            ull vpt, vsq;
            PACKF2(vpt, v.x, v.y);
            PACKF2(vsq, v.z, v.w);
            #pragma unroll
            for (int o = 0; o < 8; ++o) {
                const int j = rr - o;
                if (j >= 0 && j < 11) {
                    const int wi = (j < 6) ? j : 10 - j;
                    FMA2(accM[o], W2[wi], vpt, accM[o]);
                    FMA2(accS[o], W2[wi], vsq, accS[o]);
                }
            }
        }
        #pragma unroll
        for (int o = 0; o < 8; ++o) {
            const int oy = y0 + yb + o, ox = x0 + x;
            if (oy < OUTHW && ox < OUTHW) {
                float m1, m2, css, csq;
                UNPACKF2(m1, m2, accM[o]);
                UNPACKF2(css, csq, accS[o]);
                const float m1s = m1 * m1, m2s = m2 * m2, m12 = m1 * m2;
                const float sigsum = css - m1s - m2s;
                const float sig12  = csq - m12;
                const float num = (2.f * m12 + C1V) * (2.f * sig12 + C2V);
                const float den = (m1s + m2s + C1V) * (sigsum + C2V);
                a_ssim += __fdividef(num, den);
            }
        }
    }

    // ---- ssim reduction
    #pragma unroll
    for (int o = 16; o; o >>= 1) a_ssim += __shfl_down_sync(0xffffffffu, a_ssim, o);
    if (lane == 0) redf[warp] = a_ssim;
    __syncthreads();
    if (warp == 0) {
        float v = (lane < 8) ? redf[lane] : 0.f;
        #pragma unroll
        for (int o = 4; o; o >>= 1) v += __shfl_down_sync(0xffffffffu, v, o);
        if (lane == 0)
            atomicAdd(&g_acc[224 + ((blockIdx.x + blockIdx.y) & 31)], (double)v);
    }
}

// ---------------------------------------------------------------------------
// Parallel finalize, PDL-launched with early trigger. Divisions replaced by
// (exact 2^-22-based) reciprocal multiplies; log10 in f32. g_acc re-zeroed.
// ---------------------------------------------------------------------------
__global__ __launch_bounds__(256) void finalize_kernel(float* __restrict__ out)
{
#if __CUDA_ARCH__ >= 900
    cudaGridDependencySynchronize();
#endif
    __shared__ double s[256];
    __shared__ double g2[32];
    __shared__ double per[12];
    const int t = threadIdx.x;
    s[t] = g_acc[t];
    __syncthreads();
    g_acc[t] = 0.0;

    if (t < 32) {
        const int bs = (t < 24) ? (64 + 8 * t) : (8 * (t - 24));
        double v = 0.0;
        #pragma unroll
        for (int i = 0; i < 8; ++i) v += s[bs + i];
        g2[t] = v;
    }
    __syncthreads();

    if (t < 4) {
        const double sp  = g2[t],      st  = g2[4 + t];
        const double spp = g2[8 + t],  stt = g2[12 + t];
        const double mse = g2[16 + t] * INV_N;
        const double pm = sp * INV_N, tm = st * INV_N;
        per[t] = (pm - tm) * (pm - tm);
        const double vp = (spp - sp * sp * INV_N) * INV_NM1;
        const double vt = (stt - st * st * INV_N) * INV_NM1;
        const double ps = sqrt(fmax(vp, 0.0));
        const double ts = sqrt(fmax(vt, 0.0));
        per[4 + t] = (ps - ts) * (ps - ts);
        per[8 + t] = (mse == 0.0) ? 100.0
                   : (double)(10.0f * (LOG10_65025F - __log10f((float)mse)));
    }
    __syncthreads();

    if (t == 0) {
        const double l1  = (g2[24] + g2[25]) * INV_4N;
        const double grad = (g2[26] + g2[27] + g2[28] + g2[29]) * INV_GCNT;
        const double rng = (g2[30] + g2[31]) * INV_4N;

        const double energy = 0.25 * (per[0] + per[1] + per[2] + per[3]);
        const double dist   = 0.25 * (per[4] + per[5] + per[6] + per[7]);
        const double psnr   = 0.25 * (per[8] + per[9] + per[10] + per[11]);
        const double phys = energy + 0.5 * dist + 0.1 * rng;

        const double ss = g2[20] + g2[21] + g2[22] + g2[23];
        double ssim_mean = ss * (0.25 / ((double)OUTHW * (double)OUTHW));
        ssim_mean = fmin(fmax(ssim_mean, 0.0), 1.0);

        const double total = l1 + 0.15 * grad + 0.05 * phys + 0.1 * (1.0 - ssim_mean);
        out[0] = (float)total;
        out[1] = (float)psnr;
        out[2] = (float)ssim_mean;
    }
}

// ---------------------------------------------------------------------------
extern "C" void kernel_launch(void* const* d_in, const int* in_sizes, int n_in,
                              void* d_out, int out_size)
{
    const float* pred = (const float*)d_in[0];
    const float* tgt  = (const float*)d_in[1];
    float* out = (float*)d_out;

    cudaFuncSetAttribute(main_kernel,
                         cudaFuncAttributeMaxDynamicSharedMemorySize, SMEM_BYTES);
    dim3 g(IMG_W / TILE_W, IMG_H / TILE_H, NIMG);   // 64 x 32 x 4 = 8192
    main_kernel<<<g, 256, SMEM_BYTES>>>(pred, tgt);

    // PDL: finalize launches early (main kernel triggers at its start) and
    // parks on the grid-dependency sync until the main grid fully completes.
    cudaLaunchConfig_t cfg = {};
    cfg.gridDim = dim3(1, 1, 1);
    cfg.blockDim = dim3(256, 1, 1);
    cfg.dynamicSmemBytes = 0;
    cfg.stream = 0;
    cudaLaunchAttribute attrs[1];
    attrs[0].id = cudaLaunchAttributeProgrammaticStreamSerialization;
    attrs[0].val.programmaticStreamSerializationAllowed = 1;
    cfg.attrs = attrs;
    cfg.numAttrs = 1;
    cudaLaunchKernelEx(&cfg, finalize_kernel, out);
}